// round 5
// baseline (speedup 1.0000x reference)
#include <cuda_runtime.h>
#include <cuda_bf16.h>
#include <cstdint>

#define F_IN   128
#define F_HID  32
#define F_OUT  64
#define NDEG   11
#define MAXDEG 10
#define MAXN   100000
#define MAXE   1600000

// ---- scratch (__device__ globals; no allocation allowed) ----
__device__ int    g_is64;
__device__ int    g_deg[MAXN];
__device__ int    g_rowstart[MAXN];
__device__ int    g_cursor[MAXN];
__device__ int    g_csrc[MAXE];
__device__ int    g_bsum[256];
__device__ float  g_h2[MAXN * F_HID];    // relu(layer-1 out)
// packed weights: [d][k/4][o] as float4 over the 4 k-components
__device__ float4 g_W1p [NDEG * 32 * 32];
__device__ float4 g_Wr1p[NDEG * 32 * 32];
__device__ float4 g_W2p [NDEG * 8  * 64];
__device__ float4 g_Wr2p[NDEG * 8  * 64];

// edge_index may be int32 (jax default) or int64 (x64 enabled). Branch on flag.
__device__ __forceinline__ int edge_at(const void* ei, long long pos) {
    if (g_is64) return (int)((const long long*)ei)[pos];
    return ((const int*)ei)[pos];
}

// ---- dtype sniffer: int64 little-endian small values => odd int32 words are 0 ----
__global__ void detect_kernel(const void* ei) {
    if (blockIdx.x == 0 && threadIdx.x == 0) {
        const int* p = (const int*)ei;
        int zeros = 0;
        for (int i = 0; i < 32; i++)
            if (p[2 * i + 1] == 0) zeros++;
        g_is64 = (zeros >= 30) ? 1 : 0;
    }
}

// ---- repack weights into k-grouped float4 layout (tiny) ----
__global__ void repack_kernel(const float* __restrict__ W1, const float* __restrict__ Wr1,
                              const float* __restrict__ W2, const float* __restrict__ Wr2) {
    const int n1 = NDEG * 32 * 32;  // 11264
    const int n2 = NDEG * 8 * 64;   // 5632
    int t = blockIdx.x * blockDim.x + threadIdx.x;
    if (t < 2 * n1) {
        int u = (t < n1) ? t : t - n1;
        const float* src = (t < n1) ? W1 : Wr1;
        float4* dst = (t < n1) ? g_W1p : g_Wr1p;
        int d = u / 1024, r = u % 1024, g = r / 32, o = r % 32;
        int b = d * F_IN * F_HID + (4 * g) * F_HID + o;
        dst[u] = make_float4(src[b], src[b + F_HID], src[b + 2 * F_HID], src[b + 3 * F_HID]);
    } else if (t < 2 * n1 + 2 * n2) {
        int v = t - 2 * n1;
        int u = (v < n2) ? v : v - n2;
        const float* src = (v < n2) ? W2 : Wr2;
        float4* dst = (v < n2) ? g_W2p : g_Wr2p;
        int d = u / 512, r = u % 512, g = r / 64, o = r % 64;
        int b = d * F_HID * F_OUT + (4 * g) * F_OUT + o;
        dst[u] = make_float4(src[b], src[b + F_OUT], src[b + 2 * F_OUT], src[b + 3 * F_OUT]);
    }
}

__global__ void zero_kernel(int N) {
    int i = blockIdx.x * blockDim.x + threadIdx.x;
    if (i < N) { g_deg[i] = 0; g_cursor[i] = 0; }
}

// ---- degree count: int REDs only ----
__global__ void count_kernel(const void* __restrict__ ei, int E, int N) {
    int e = blockIdx.x * blockDim.x + threadIdx.x;
    if (e >= E) return;
    int dst = edge_at(ei, (long long)E + e);
    if ((unsigned)dst >= (unsigned)N) return;  // defensive
    atomicAdd(&g_deg[dst], 1);
}

// ---- exclusive scan of g_deg -> g_rowstart (3 stages) ----
__global__ void scan1_kernel(int N) {
    __shared__ int s[1024];
    int i = blockIdx.x * 1024 + threadIdx.x;
    int v = (i < N) ? g_deg[i] : 0;
    s[threadIdx.x] = v;
    __syncthreads();
    for (int off = 1; off < 1024; off <<= 1) {
        int t = (threadIdx.x >= off) ? s[threadIdx.x - off] : 0;
        __syncthreads();
        s[threadIdx.x] += t;
        __syncthreads();
    }
    if (i < N) g_rowstart[i] = s[threadIdx.x] - v;  // exclusive
    if (threadIdx.x == 1023) g_bsum[blockIdx.x] = s[1023];
}

__global__ void scan2_kernel(int nb) {
    if (threadIdx.x == 0) {
        int acc = 0;
        for (int b = 0; b < nb; b++) { int t = g_bsum[b]; g_bsum[b] = acc; acc += t; }
    }
}

__global__ void scan3_kernel(int N) {
    int i = blockIdx.x * blockDim.x + threadIdx.x;
    if (i < N) g_rowstart[i] += g_bsum[i >> 10];
}

// ---- CSR fill ----
__global__ void fill_kernel(const void* __restrict__ ei, int E, int N) {
    int e = blockIdx.x * blockDim.x + threadIdx.x;
    if (e >= E) return;
    int src = edge_at(ei, e);
    int dst = edge_at(ei, (long long)E + e);
    if ((unsigned)dst >= (unsigned)N || (unsigned)src >= (unsigned)N) return;  // defensive
    int pos = atomicAdd(&g_cursor[dst], 1);
    g_csrc[g_rowstart[dst] + pos] = src;
}

// ---- fused layer-1: warp per node; gather-aggregate in regs, then GEMV ----
__global__ void layer1_kernel(const float* __restrict__ x, const float* __restrict__ b1, int N) {
    __shared__ float sh[8][256];  // per warp: h[128] | x[128]
    int warp = threadIdx.x >> 5, lane = threadIdx.x & 31;
    int n = blockIdx.x * 8 + warp;
    if (n >= N) return;
    int d = g_deg[n];
    int start = g_rowstart[n];
    const float4* xv = (const float4*)x;
    float4 hacc = make_float4(0.f, 0.f, 0.f, 0.f);
#pragma unroll 4
    for (int k = 0; k < d; k++) {
        int s = g_csrc[start + k];
        float4 v = xv[(size_t)s * 32 + lane];
        hacc.x += v.x; hacc.y += v.y; hacc.z += v.z; hacc.w += v.w;
    }
    ((float4*)&sh[warp][0])[lane]   = hacc;
    ((float4*)&sh[warp][128])[lane] = xv[(size_t)n * 32 + lane];
    __syncwarp();
    int dc = min(d, MAXDEG);
    float acc = b1[dc * F_HID + lane];
    const float4* w1 = &g_W1p [dc * 1024 + lane];
    const float4* wr = &g_Wr1p[dc * 1024 + lane];
#pragma unroll 8
    for (int g = 0; g < 32; g++) {
        float4 hh = *(const float4*)&sh[warp][4 * g];
        float4 xx = *(const float4*)&sh[warp][128 + 4 * g];
        float4 a = w1[g * 32];
        float4 b = wr[g * 32];
        acc += hh.x * a.x + hh.y * a.y + hh.z * a.z + hh.w * a.w
             + xx.x * b.x + xx.y * b.y + xx.z * b.z + xx.w * b.w;
    }
    g_h2[(size_t)n * F_HID + lane] = fmaxf(acc, 0.f);
}

// ---- fused layer-2: warp per node; lane owns one hidden component ----
__global__ void layer2_kernel(const float* __restrict__ b2, float* __restrict__ out, int N) {
    __shared__ float sh[8][64];  // per warp: agg[32] | h2[32]
    int warp = threadIdx.x >> 5, lane = threadIdx.x & 31;
    int n = blockIdx.x * 8 + warp;
    if (n >= N) return;
    int d = g_deg[n];
    int start = g_rowstart[n];
    float hacc = 0.f;
#pragma unroll 4
    for (int k = 0; k < d; k++) {
        int s = g_csrc[start + k];
        hacc += g_h2[(size_t)s * F_HID + lane];
    }
    sh[warp][lane]      = hacc;
    sh[warp][32 + lane] = g_h2[(size_t)n * F_HID + lane];
    __syncwarp();
    int dc = min(d, MAXDEG);
    float acc0 = b2[dc * F_OUT + lane];
    float acc1 = b2[dc * F_OUT + 32 + lane];
    const float4* w2  = &g_W2p [dc * 512];
    const float4* wr2 = &g_Wr2p[dc * 512];
#pragma unroll
    for (int g = 0; g < 8; g++) {
        float4 hh = *(const float4*)&sh[warp][4 * g];
        float4 xx = *(const float4*)&sh[warp][32 + 4 * g];
        float4 a0 = w2 [g * 64 + lane];
        float4 a1 = w2 [g * 64 + 32 + lane];
        float4 r0 = wr2[g * 64 + lane];
        float4 r1 = wr2[g * 64 + 32 + lane];
        acc0 += hh.x * a0.x + hh.y * a0.y + hh.z * a0.z + hh.w * a0.w
              + xx.x * r0.x + xx.y * r0.y + xx.z * r0.z + xx.w * r0.w;
        acc1 += hh.x * a1.x + hh.y * a1.y + hh.z * a1.z + hh.w * a1.w
              + xx.x * r1.x + xx.y * r1.y + xx.z * r1.z + xx.w * r1.w;
    }
    out[(size_t)n * F_OUT + lane]      = acc0;
    out[(size_t)n * F_OUT + 32 + lane] = acc1;
}

extern "C" void kernel_launch(void* const* d_in, const int* in_sizes, int n_in,
                              void* d_out, int out_size) {
    const float* x   = (const float*)d_in[0];
    const void*  ei  = d_in[1];
    const float* W1  = (const float*)d_in[2];
    const float* b1  = (const float*)d_in[3];
    const float* Wr1 = (const float*)d_in[4];
    const float* W2  = (const float*)d_in[5];
    const float* b2  = (const float*)d_in[6];
    const float* Wr2 = (const float*)d_in[7];

    int N = in_sizes[0] / F_IN;
    int E = in_sizes[1] / 2;
    int nb = (N + 1023) / 1024;

    detect_kernel<<<1, 32>>>(ei);
    int repack_threads = 2 * (NDEG * 32 * 32) + 2 * (NDEG * 8 * 64);
    repack_kernel<<<(repack_threads + 255) / 256, 256>>>(W1, Wr1, W2, Wr2);
    zero_kernel<<<(N + 255) / 256, 256>>>(N);
    count_kernel<<<(E + 255) / 256, 256>>>(ei, E, N);
    scan1_kernel<<<nb, 1024>>>(N);
    scan2_kernel<<<1, 32>>>(nb);
    scan3_kernel<<<(N + 255) / 256, 256>>>(N);
    fill_kernel<<<(E + 255) / 256, 256>>>(ei, E, N);
    layer1_kernel<<<(N + 7) / 8, 256>>>(x, b1, N);
    layer2_kernel<<<(N + 7) / 8, 256>>>(b2, (float*)d_out, N);
}

// round 9
// speedup vs baseline: 1.0288x; 1.0288x over previous
#include <cuda_runtime.h>
#include <cuda_bf16.h>
#include <cstdint>

#define F_IN   128
#define F_HID  32
#define F_OUT  64
#define NDEG   11
#define MAXDEG 10
#define MAXN   100000
#define MAXE   1600000

// ---- scratch (__device__ globals; no allocation allowed) ----
__device__ int    g_is64;
__device__ int    g_deg[MAXN];
__device__ int    g_rowstart[MAXN];
__device__ int    g_cursor[MAXN];
__device__ int    g_csrc[MAXE];
__device__ int    g_bsum[256];
__device__ float  g_h2[MAXN * F_HID];    // relu(layer-1 out)
// packed weights: [d][k/4][o] as float4 over the 4 k-components
__device__ float4 g_W1p [NDEG * 32 * 32];
__device__ float4 g_Wr1p[NDEG * 32 * 32];
__device__ float4 g_W2p [NDEG * 8  * 64];
__device__ float4 g_Wr2p[NDEG * 8  * 64];

// edge_index may be int32 (jax default) or int64 (x64 enabled). Branch on flag.
__device__ __forceinline__ int edge_at(const void* ei, long long pos) {
    if (g_is64) return (int)((const long long*)ei)[pos];
    return ((const int*)ei)[pos];
}

// ---- zero + dtype sniff fused ----
__global__ void zero_detect_kernel(const void* ei, int N) {
    int i = blockIdx.x * blockDim.x + threadIdx.x;
    if (i < N) { g_deg[i] = 0; g_cursor[i] = 0; }
    if (blockIdx.x == 0 && threadIdx.x == 0) {
        const int* p = (const int*)ei;
        int zeros = 0;
#pragma unroll
        for (int j = 0; j < 32; j++)
            if (p[2 * j + 1] == 0) zeros++;
        g_is64 = (zeros >= 30) ? 1 : 0;
    }
}

// ---- repack weights into k-grouped float4 layout (tiny) ----
__global__ void repack_kernel(const float* __restrict__ W1, const float* __restrict__ Wr1,
                              const float* __restrict__ W2, const float* __restrict__ Wr2) {
    const int n1 = NDEG * 32 * 32;  // 11264
    const int n2 = NDEG * 8 * 64;   // 5632
    int t = blockIdx.x * blockDim.x + threadIdx.x;
    if (t < 2 * n1) {
        int u = (t < n1) ? t : t - n1;
        const float* src = (t < n1) ? W1 : Wr1;
        float4* dst = (t < n1) ? g_W1p : g_Wr1p;
        int d = u / 1024, r = u % 1024, g = r / 32, o = r % 32;
        int b = d * F_IN * F_HID + (4 * g) * F_HID + o;
        dst[u] = make_float4(src[b], src[b + F_HID], src[b + 2 * F_HID], src[b + 3 * F_HID]);
    } else if (t < 2 * n1 + 2 * n2) {
        int v = t - 2 * n1;
        int u = (v < n2) ? v : v - n2;
        const float* src = (v < n2) ? W2 : Wr2;
        float4* dst = (v < n2) ? g_W2p : g_Wr2p;
        int d = u / 512, r = u % 512, g = r / 64, o = r % 64;
        int b = d * F_HID * F_OUT + (4 * g) * F_OUT + o;
        dst[u] = make_float4(src[b], src[b + F_OUT], src[b + 2 * F_OUT], src[b + 3 * F_OUT]);
    }
}

// ---- degree count: int REDs only ----
__global__ void count_kernel(const void* __restrict__ ei, int E, int N) {
    int e = blockIdx.x * blockDim.x + threadIdx.x;
    if (e >= E) return;
    int dst = edge_at(ei, (long long)E + e);
    if ((unsigned)dst >= (unsigned)N) return;  // defensive
    atomicAdd(&g_deg[dst], 1);
}

// ---- exclusive scan of g_deg -> g_rowstart (3 stages) ----
__global__ void scan1_kernel(int N) {
    __shared__ int s[1024];
    int i = blockIdx.x * 1024 + threadIdx.x;
    int v = (i < N) ? g_deg[i] : 0;
    s[threadIdx.x] = v;
    __syncthreads();
    for (int off = 1; off < 1024; off <<= 1) {
        int t = (threadIdx.x >= off) ? s[threadIdx.x - off] : 0;
        __syncthreads();
        s[threadIdx.x] += t;
        __syncthreads();
    }
    if (i < N) g_rowstart[i] = s[threadIdx.x] - v;  // exclusive
    if (threadIdx.x == 1023) g_bsum[blockIdx.x] = s[1023];
}

// parallel single-block exclusive scan over block sums (was a serial 1-thread loop)
__global__ void scan2_kernel(int nb) {
    __shared__ int s[256];
    int v = (threadIdx.x < nb) ? g_bsum[threadIdx.x] : 0;
    s[threadIdx.x] = v;
    __syncthreads();
    for (int off = 1; off < 256; off <<= 1) {
        int t = (threadIdx.x >= off) ? s[threadIdx.x - off] : 0;
        __syncthreads();
        s[threadIdx.x] += t;
        __syncthreads();
    }
    if (threadIdx.x < nb) g_bsum[threadIdx.x] = s[threadIdx.x] - v;  // exclusive
}

__global__ void scan3_kernel(int N) {
    int i = blockIdx.x * blockDim.x + threadIdx.x;
    if (i < N) g_rowstart[i] += g_bsum[i >> 10];
}

// ---- CSR fill ----
__global__ void fill_kernel(const void* __restrict__ ei, int E, int N) {
    int e = blockIdx.x * blockDim.x + threadIdx.x;
    if (e >= E) return;
    int src = edge_at(ei, e);
    int dst = edge_at(ei, (long long)E + e);
    if ((unsigned)dst >= (unsigned)N || (unsigned)src >= (unsigned)N) return;  // defensive
    int pos = atomicAdd(&g_cursor[dst], 1);
    g_csrc[g_rowstart[dst] + pos] = src;
}

// ---- fused layer-1: warp per node; batched gather (MLP=8), then GEMV ----
__global__ void layer1_kernel(const float* __restrict__ x, const float* __restrict__ b1, int N) {
    __shared__ float sh[8][256];  // per warp: h[128] | x[128]
    int warp = threadIdx.x >> 5, lane = threadIdx.x & 31;
    int n = blockIdx.x * 8 + warp;
    if (n >= N) return;
    int d = g_deg[n];
    int start = g_rowstart[n];
    const float4* xv = (const float4*)x;
    float4 hacc = make_float4(0.f, 0.f, 0.f, 0.f);

    int k = 0;
    for (; k + 8 <= d; k += 8) {
        // 8 broadcast index loads, then 8 independent 16B gathers in flight
        int s0 = g_csrc[start + k + 0];
        int s1 = g_csrc[start + k + 1];
        int s2 = g_csrc[start + k + 2];
        int s3 = g_csrc[start + k + 3];
        int s4 = g_csrc[start + k + 4];
        int s5 = g_csrc[start + k + 5];
        int s6 = g_csrc[start + k + 6];
        int s7 = g_csrc[start + k + 7];
        float4 v0 = xv[(size_t)s0 * 32 + lane];
        float4 v1 = xv[(size_t)s1 * 32 + lane];
        float4 v2 = xv[(size_t)s2 * 32 + lane];
        float4 v3 = xv[(size_t)s3 * 32 + lane];
        float4 v4 = xv[(size_t)s4 * 32 + lane];
        float4 v5 = xv[(size_t)s5 * 32 + lane];
        float4 v6 = xv[(size_t)s6 * 32 + lane];
        float4 v7 = xv[(size_t)s7 * 32 + lane];
        hacc.x += ((v0.x + v1.x) + (v2.x + v3.x)) + ((v4.x + v5.x) + (v6.x + v7.x));
        hacc.y += ((v0.y + v1.y) + (v2.y + v3.y)) + ((v4.y + v5.y) + (v6.y + v7.y));
        hacc.z += ((v0.z + v1.z) + (v2.z + v3.z)) + ((v4.z + v5.z) + (v6.z + v7.z));
        hacc.w += ((v0.w + v1.w) + (v2.w + v3.w)) + ((v4.w + v5.w) + (v6.w + v7.w));
    }
    for (; k < d; k++) {
        int s = g_csrc[start + k];
        float4 v = xv[(size_t)s * 32 + lane];
        hacc.x += v.x; hacc.y += v.y; hacc.z += v.z; hacc.w += v.w;
    }

    ((float4*)&sh[warp][0])[lane]   = hacc;
    ((float4*)&sh[warp][128])[lane] = xv[(size_t)n * 32 + lane];
    __syncwarp();
    int dc = min(d, MAXDEG);
    float acc = b1[dc * F_HID + lane];
    const float4* w1 = &g_W1p [dc * 1024 + lane];
    const float4* wr = &g_Wr1p[dc * 1024 + lane];
#pragma unroll 8
    for (int g = 0; g < 32; g++) {
        float4 hh = *(const float4*)&sh[warp][4 * g];
        float4 xx = *(const float4*)&sh[warp][128 + 4 * g];
        float4 a = w1[g * 32];
        float4 b = wr[g * 32];
        acc += hh.x * a.x + hh.y * a.y + hh.z * a.z + hh.w * a.w
             + xx.x * b.x + xx.y * b.y + xx.z * b.z + xx.w * b.w;
    }
    g_h2[(size_t)n * F_HID + lane] = fmaxf(acc, 0.f);
}

// ---- fused layer-2: warp per node; batched gather (MLP=4) ----
__global__ void layer2_kernel(const float* __restrict__ b2, float* __restrict__ out, int N) {
    __shared__ float sh[8][64];  // per warp: agg[32] | h2[32]
    int warp = threadIdx.x >> 5, lane = threadIdx.x & 31;
    int n = blockIdx.x * 8 + warp;
    if (n >= N) return;
    int d = g_deg[n];
    int start = g_rowstart[n];
    float hacc = 0.f;
    int k = 0;
    for (; k + 4 <= d; k += 4) {
        int s0 = g_csrc[start + k + 0];
        int s1 = g_csrc[start + k + 1];
        int s2 = g_csrc[start + k + 2];
        int s3 = g_csrc[start + k + 3];
        float v0 = g_h2[(size_t)s0 * F_HID + lane];
        float v1 = g_h2[(size_t)s1 * F_HID + lane];
        float v2 = g_h2[(size_t)s2 * F_HID + lane];
        float v3 = g_h2[(size_t)s3 * F_HID + lane];
        hacc += (v0 + v1) + (v2 + v3);
    }
    for (; k < d; k++) {
        int s = g_csrc[start + k];
        hacc += g_h2[(size_t)s * F_HID + lane];
    }
    sh[warp][lane]      = hacc;
    sh[warp][32 + lane] = g_h2[(size_t)n * F_HID + lane];
    __syncwarp();
    int dc = min(d, MAXDEG);
    float acc0 = b2[dc * F_OUT + lane];
    float acc1 = b2[dc * F_OUT + 32 + lane];
    const float4* w2  = &g_W2p [dc * 512];
    const float4* wr2 = &g_Wr2p[dc * 512];
#pragma unroll
    for (int g = 0; g < 8; g++) {
        float4 hh = *(const float4*)&sh[warp][4 * g];
        float4 xx = *(const float4*)&sh[warp][32 + 4 * g];
        float4 a0 = w2 [g * 64 + lane];
        float4 a1 = w2 [g * 64 + 32 + lane];
        float4 r0 = wr2[g * 64 + lane];
        float4 r1 = wr2[g * 64 + 32 + lane];
        acc0 += hh.x * a0.x + hh.y * a0.y + hh.z * a0.z + hh.w * a0.w
              + xx.x * r0.x + xx.y * r0.y + xx.z * r0.z + xx.w * r0.w;
        acc1 += hh.x * a1.x + hh.y * a1.y + hh.z * a1.z + hh.w * a1.w
              + xx.x * r1.x + xx.y * r1.y + xx.z * r1.z + xx.w * r1.w;
    }
    out[(size_t)n * F_OUT + lane]      = acc0;
    out[(size_t)n * F_OUT + 32 + lane] = acc1;
}

extern "C" void kernel_launch(void* const* d_in, const int* in_sizes, int n_in,
                              void* d_out, int out_size) {
    const float* x   = (const float*)d_in[0];
    const void*  ei  = d_in[1];
    const float* W1  = (const float*)d_in[2];
    const float* b1  = (const float*)d_in[3];
    const float* Wr1 = (const float*)d_in[4];
    const float* W2  = (const float*)d_in[5];
    const float* b2  = (const float*)d_in[6];
    const float* Wr2 = (const float*)d_in[7];

    int N = in_sizes[0] / F_IN;
    int E = in_sizes[1] / 2;
    int nb = (N + 1023) / 1024;

    zero_detect_kernel<<<(N + 255) / 256, 256>>>(ei, N);
    int repack_threads = 2 * (NDEG * 32 * 32) + 2 * (NDEG * 8 * 64);
    repack_kernel<<<(repack_threads + 255) / 256, 256>>>(W1, Wr1, W2, Wr2);
    count_kernel<<<(E + 255) / 256, 256>>>(ei, E, N);
    scan1_kernel<<<nb, 1024>>>(N);
    scan2_kernel<<<1, 256>>>(nb);
    scan3_kernel<<<(N + 255) / 256, 256>>>(N);
    fill_kernel<<<(E + 255) / 256, 256>>>(ei, E, N);
    layer1_kernel<<<(N + 7) / 8, 256>>>(x, b1, N);
    layer2_kernel<<<(N + 7) / 8, 256>>>(b2, (float*)d_out, N);
}